// round 14
// baseline (speedup 1.0000x reference)
#include <cuda_runtime.h>
#include <cuda_fp16.h>
#include <cstdint>
#include <cstddef>

#define MAXN 100000
#define MAXE 3200000

// Scratch (device globals: allocation-free, rewritten every replay)
__device__ __half g_bufA[MAXN * 128];  // fp16 ping
__device__ __half g_bufB[MAXN * 128];  // fp16 pong
__device__ float  g_dinv[MAXN];
__device__ int    g_deg[MAXN];
__device__ int    g_offs[MAXN + 1];
__device__ int    g_cur[MAXN];
__device__ int    g_csr[MAXE];         // edge sources grouped by destination
__device__ int    g_part[128];

__device__ __forceinline__ uint32_t smem_u32(const void* p) {
    return (uint32_t)__cvta_generic_to_shared(p);
}

// ---------------------------------------------------------------------------
// Degree / dinv / CSR build  (deg zeroed by cudaMemsetAsync host-side)
// 8 edges per thread: 8 independent atomics in flight (ATOMG lat ~318cyc).
// ---------------------------------------------------------------------------
__global__ void k_count(const int* __restrict__ col, int E) {
    int t = blockIdx.x * blockDim.x + threadIdx.x;
    int e0 = t * 8;
    if (e0 + 7 < E) {
        int4 c0 = __ldg((const int4*)(col + e0));
        int4 c1 = __ldg((const int4*)(col + e0 + 4));
        atomicAdd(&g_deg[c0.x], 1); atomicAdd(&g_deg[c0.y], 1);
        atomicAdd(&g_deg[c0.z], 1); atomicAdd(&g_deg[c0.w], 1);
        atomicAdd(&g_deg[c1.x], 1); atomicAdd(&g_deg[c1.y], 1);
        atomicAdd(&g_deg[c1.z], 1); atomicAdd(&g_deg[c1.w], 1);
    } else {
        for (int e = e0; e < E; e++) atomicAdd(&g_deg[col[e]], 1);
    }
}

__global__ __launch_bounds__(1024) void k_scan1(int n) {
    __shared__ int sh[1024];
    int i = blockIdx.x * 1024 + threadIdx.x;
    int v = (i < n) ? g_deg[i] : 0;
    sh[threadIdx.x] = v;
    __syncthreads();
    for (int d = 1; d < 1024; d <<= 1) {
        int t = (threadIdx.x >= d) ? sh[threadIdx.x - d] : 0;
        __syncthreads();
        sh[threadIdx.x] += t;
        __syncthreads();
    }
    if (i < n) g_offs[i] = sh[threadIdx.x] - v;  // exclusive within block
    if (threadIdx.x == 1023) g_part[blockIdx.x] = sh[1023];
}

// Merged: scan block partials (redundantly per block), add offset,
// cursor = start offset, dinv, sentinel.
__global__ __launch_bounds__(256) void k_finish(int n, int E, int nb) {
    __shared__ int sp[128];
    int tid = threadIdx.x;
    if (tid < 128) sp[tid] = (tid < nb) ? g_part[tid] : 0;
    __syncthreads();
    for (int d = 1; d < 128; d <<= 1) {
        int t = 0;
        if (tid < 128 && tid >= d) t = sp[tid - d];
        __syncthreads();
        if (tid < 128) sp[tid] += t;
        __syncthreads();
    }
    int i = blockIdx.x * 256 + tid;
    if (i < n) {
        int b = i >> 10;
        int off = (b == 0) ? 0 : sp[b - 1];
        int o = g_offs[i] + off;
        g_offs[i] = o;
        g_cur[i]  = o;  // fill cursor starts at segment base
        g_dinv[i] = rsqrtf((float)g_deg[i] + 1.0f);
    }
    if (i == 0) g_offs[n] = E;
}

__global__ void k_fill(const int* __restrict__ row, const int* __restrict__ col, int E) {
    int t = blockIdx.x * blockDim.x + threadIdx.x;
    int e0 = t * 8;
    if (e0 + 7 < E) {
        int4 c0 = __ldg((const int4*)(col + e0));
        int4 c1 = __ldg((const int4*)(col + e0 + 4));
        int4 r0 = __ldg((const int4*)(row + e0));
        int4 r1 = __ldg((const int4*)(row + e0 + 4));
        int p0 = atomicAdd(&g_cur[c0.x], 1);
        int p1 = atomicAdd(&g_cur[c0.y], 1);
        int p2 = atomicAdd(&g_cur[c0.z], 1);
        int p3 = atomicAdd(&g_cur[c0.w], 1);
        int p4 = atomicAdd(&g_cur[c1.x], 1);
        int p5 = atomicAdd(&g_cur[c1.y], 1);
        int p6 = atomicAdd(&g_cur[c1.z], 1);
        int p7 = atomicAdd(&g_cur[c1.w], 1);
        g_csr[p0] = r0.x; g_csr[p1] = r0.y; g_csr[p2] = r0.z; g_csr[p3] = r0.w;
        g_csr[p4] = r1.x; g_csr[p5] = r1.y; g_csr[p6] = r1.z; g_csr[p7] = r1.w;
    } else {
        for (int e = e0; e < E; e++) {
            int p = atomicAdd(&g_cur[col[e]], 1);
            g_csr[p] = row[e];
        }
    }
}

// ---------------------------------------------------------------------------
// Tensor-core GEMM (mma.sync m16n8k16, f16 x f16 -> f32).
// Block = 128 threads (4 warps), tile = 64 nodes x FO.
// PRO 0: A = fp16 input raw.     PRO 2: A = f16(dinv * fp32 input)   (L1)
// EPI 0: outh = f16(dot)
// EPI 1: outh = f16(dinv * relu(dinv * dot + bepi))
// EPI 2: outh = f16(relu(dinv * dot + bepi))
// EPI 3: outf = dot + bepi
// ---------------------------------------------------------------------------
template <int FI, int FO, int PRO, int EPI>
__global__ __launch_bounds__(128)
void k_tgemm(const __half* __restrict__ inh, const float* __restrict__ inf,
             const float* __restrict__ W, const float* __restrict__ bepi,
             __half* __restrict__ outh, float* __restrict__ outf, int n)
{
    constexpr int SA = FI + 8;
    constexpr int SW = FO + 8;
    extern __shared__ char smraw[];
    __half* sA = (__half*)smraw;            // 64 x SA
    __half* sW = (__half*)smraw + 64 * SA;  // FI x SW

    const int tid   = threadIdx.x;
    const int node0 = blockIdx.x * 64;

    if (PRO == 0) {
        for (int i = tid; i < 64 * (FI / 8); i += 128) {
            int node = i / (FI / 8);
            int f8   = i % (FI / 8);
            int gn   = node0 + node;
            uint4 v = make_uint4(0, 0, 0, 0);
            if (gn < n) v = *(const uint4*)(inh + (size_t)gn * FI + f8 * 8);
            *(uint4*)(sA + node * SA + f8 * 8) = v;
        }
    } else {
        for (int i = tid; i < 64 * (FI / 4); i += 128) {
            int node = i / (FI / 4);
            int fc   = i % (FI / 4);
            int f    = fc * 4;
            int gn   = node0 + node;
            float4 v = make_float4(0.f, 0.f, 0.f, 0.f);
            float dv = 0.f;
            if (gn < n) {
                v = *(const float4*)(inf + (size_t)gn * FI + f);
                dv = g_dinv[gn];
            }
            __half2 h01 = __floats2half2_rn(v.x * dv, v.y * dv);
            __half2 h23 = __floats2half2_rn(v.z * dv, v.w * dv);
            *(uint2*)(sA + node * SA + f) = make_uint2(*(uint32_t*)&h01, *(uint32_t*)&h23);
        }
    }
    for (int i = tid; i < FI * (FO / 4); i += 128) {
        int k  = i / (FO / 4);
        int nc = i % (FO / 4);
        int nn = nc * 4;
        float4 w = __ldg((const float4*)(W + (size_t)k * FO + nn));
        __half2 h01 = __floats2half2_rn(w.x, w.y);
        __half2 h23 = __floats2half2_rn(w.z, w.w);
        *(uint2*)(sW + k * SW + nn) = make_uint2(*(uint32_t*)&h01, *(uint32_t*)&h23);
    }
    __syncthreads();

    const int w    = tid >> 5;
    const int lane = tid & 31;
    constexpr int NT = FO / 8;

    float acc[NT][4];
    #pragma unroll
    for (int t = 0; t < NT; t++) {
        acc[t][0] = 0.f; acc[t][1] = 0.f; acc[t][2] = 0.f; acc[t][3] = 0.f;
    }

    const uint32_t aBase = smem_u32(sA);
    const uint32_t wBase = smem_u32(sW);
    const int arow = w * 16 + (lane & 15);
    const int asel = (lane >> 4) * 8;

    #pragma unroll
    for (int kk = 0; kk < FI / 16; kk++) {
        uint32_t a0, a1, a2, a3;
        {
            uint32_t addrA = aBase + (uint32_t)((arow * SA + kk * 16 + asel) * 2);
            asm volatile("ldmatrix.sync.aligned.m8n8.x4.shared.b16 {%0,%1,%2,%3}, [%4];"
                         : "=r"(a0), "=r"(a1), "=r"(a2), "=r"(a3) : "r"(addrA));
        }
        const int krow = kk * 16 + (lane & 15);
        #pragma unroll
        for (int nt = 0; nt < NT; nt++) {
            uint32_t b0, b1;
            uint32_t addrB = wBase + (uint32_t)((krow * SW + nt * 8) * 2);
            asm volatile("ldmatrix.sync.aligned.m8n8.x2.trans.shared.b16 {%0,%1}, [%2];"
                         : "=r"(b0), "=r"(b1) : "r"(addrB));
            asm volatile("mma.sync.aligned.m16n8k16.row.col.f32.f16.f16.f32 "
                         "{%0,%1,%2,%3}, {%4,%5,%6,%7}, {%8,%9}, {%0,%1,%2,%3};"
                         : "+f"(acc[nt][0]), "+f"(acc[nt][1]),
                           "+f"(acc[nt][2]), "+f"(acc[nt][3])
                         : "r"(a0), "r"(a1), "r"(a2), "r"(a3), "r"(b0), "r"(b1));
        }
    }

    const int g8 = lane >> 2;
    const int t2 = (lane & 3) * 2;
    const int r0 = node0 + w * 16 + g8;
    const int r1 = r0 + 8;
    float dv0 = 0.f, dv1 = 0.f;
    if (EPI == 1 || EPI == 2) {
        if (r0 < n) dv0 = g_dinv[r0];
        if (r1 < n) dv1 = g_dinv[r1];
    }
    #pragma unroll
    for (int nt = 0; nt < NT; nt++) {
        int c = nt * 8 + t2;
        float d0 = acc[nt][0], d1 = acc[nt][1], d2 = acc[nt][2], d3 = acc[nt][3];
        if (EPI == 0) {
            if (r0 < n) {
                __half2 hh = __floats2half2_rn(d0, d1);
                *(uint32_t*)(outh + (size_t)r0 * FO + c) = *(uint32_t*)&hh;
            }
            if (r1 < n) {
                __half2 hh = __floats2half2_rn(d2, d3);
                *(uint32_t*)(outh + (size_t)r1 * FO + c) = *(uint32_t*)&hh;
            }
        } else if (EPI == 1 || EPI == 2) {
            float bc0 = __ldg(bepi + c), bc1 = __ldg(bepi + c + 1);
            if (r0 < n) {
                float v0 = fmaxf(fmaf(d0, dv0, bc0), 0.f);
                float v1 = fmaxf(fmaf(d1, dv0, bc1), 0.f);
                if (EPI == 1) { v0 *= dv0; v1 *= dv0; }
                __half2 hh = __floats2half2_rn(v0, v1);
                *(uint32_t*)(outh + (size_t)r0 * FO + c) = *(uint32_t*)&hh;
            }
            if (r1 < n) {
                float v0 = fmaxf(fmaf(d2, dv1, bc0), 0.f);
                float v1 = fmaxf(fmaf(d3, dv1, bc1), 0.f);
                if (EPI == 1) { v0 *= dv1; v1 *= dv1; }
                __half2 hh = __floats2half2_rn(v0, v1);
                *(uint32_t*)(outh + (size_t)r1 * FO + c) = *(uint32_t*)&hh;
            }
        } else {
            float add0 = __ldg(bepi + c), add1 = __ldg(bepi + c + 1);
            if (r0 < n) *(float2*)(outf + (size_t)r0 * FO + c) = make_float2(d0 + add0, d1 + add1);
            if (r1 < n) *(float2*)(outf + (size_t)r1 * FO + c) = make_float2(d2 + add0, d3 + add1);
        }
    }
}

// ---------------------------------------------------------------------------
// CSR gather-reduce (fp16 in, fp32 accumulate, fp16 out).
// 8-byte lane loads (HPL=4), 8-edge unroll -> MLP=8 per lane.
// GM 0: out = f16(s)          GM 1: out = f16(dinv * relu(dinv * s + bias))
// ---------------------------------------------------------------------------
template <int FO, int GM>
__global__ __launch_bounds__(256)
void k_gather(const __half* __restrict__ gsrc, __half* __restrict__ gdst,
              const float* __restrict__ bias, int n)
{
    constexpr int HPL = 4;                 // halves per lane (8B loads)
    constexpr int LPN = FO / HPL;          // lanes per node
    constexpr int NPW = 32 / LPN;          // nodes per warp

    int warp = (blockIdx.x * 256 + threadIdx.x) >> 5;
    int lane = threadIdx.x & 31;
    int node = warp * NPW + lane / LPN;
    if (node >= n) return;
    int li  = lane % LPN;
    int beg = g_offs[node];
    int end = g_offs[node + 1];

    const __half* base = gsrc + li * HPL;

    float a0, a1, a2, a3;
    {
        uint2 u = __ldg((const uint2*)(base + (size_t)node * FO));
        float2 f0 = __half22float2(*(__half2*)&u.x);
        float2 f1 = __half22float2(*(__half2*)&u.y);
        a0 = f0.x; a1 = f0.y; a2 = f1.x; a3 = f1.y;
    }

    auto addrow = [&](int s) {
        uint2 u = __ldg((const uint2*)(base + (size_t)s * FO));
        float2 f0 = __half22float2(*(__half2*)&u.x);
        float2 f1 = __half22float2(*(__half2*)&u.y);
        a0 += f0.x; a1 += f0.y; a2 += f1.x; a3 += f1.y;
    };

    int e = beg;
    while (e < end && (e & 3)) { addrow(__ldg(g_csr + e)); e++; }

    for (; e + 7 < end; e += 8) {
        int4 iv0 = __ldg((const int4*)(g_csr + e));
        int4 iv1 = __ldg((const int4*)(g_csr + e + 4));
        int idx[8] = {iv0.x, iv0.y, iv0.z, iv0.w, iv1.x, iv1.y, iv1.z, iv1.w};
        uint2 us[8];
        #pragma unroll
        for (int q = 0; q < 8; q++)
            us[q] = __ldg((const uint2*)(base + (size_t)idx[q] * FO));
        float x0[8], x1[8], x2[8], x3[8];
        #pragma unroll
        for (int q = 0; q < 8; q++) {
            float2 f0 = __half22float2(*(__half2*)&us[q].x);
            float2 f1 = __half22float2(*(__half2*)&us[q].y);
            x0[q] = f0.x; x1[q] = f0.y; x2[q] = f1.x; x3[q] = f1.y;
        }
        a0 += ((x0[0] + x0[1]) + (x0[2] + x0[3])) + ((x0[4] + x0[5]) + (x0[6] + x0[7]));
        a1 += ((x1[0] + x1[1]) + (x1[2] + x1[3])) + ((x1[4] + x1[5]) + (x1[6] + x1[7]));
        a2 += ((x2[0] + x2[1]) + (x2[2] + x2[3])) + ((x2[4] + x2[5]) + (x2[6] + x2[7]));
        a3 += ((x3[0] + x3[1]) + (x3[2] + x3[3])) + ((x3[4] + x3[5]) + (x3[6] + x3[7]));
    }
    for (; e + 3 < end; e += 4) {
        int4 iv = __ldg((const int4*)(g_csr + e));
        uint2 u0 = __ldg((const uint2*)(base + (size_t)iv.x * FO));
        uint2 u1 = __ldg((const uint2*)(base + (size_t)iv.y * FO));
        uint2 u2 = __ldg((const uint2*)(base + (size_t)iv.z * FO));
        uint2 u3 = __ldg((const uint2*)(base + (size_t)iv.w * FO));
        float2 f0a = __half22float2(*(__half2*)&u0.x), f0b = __half22float2(*(__half2*)&u0.y);
        float2 f1a = __half22float2(*(__half2*)&u1.x), f1b = __half22float2(*(__half2*)&u1.y);
        float2 f2a = __half22float2(*(__half2*)&u2.x), f2b = __half22float2(*(__half2*)&u2.y);
        float2 f3a = __half22float2(*(__half2*)&u3.x), f3b = __half22float2(*(__half2*)&u3.y);
        a0 += (f0a.x + f1a.x) + (f2a.x + f3a.x);
        a1 += (f0a.y + f1a.y) + (f2a.y + f3a.y);
        a2 += (f0b.x + f1b.x) + (f2b.x + f3b.x);
        a3 += (f0b.y + f1b.y) + (f2b.y + f3b.y);
    }
    for (; e < end; e++) addrow(__ldg(g_csr + e));

    float v0, v1, v2, v3;
    if (GM == 0) {
        v0 = a0; v1 = a1; v2 = a2; v3 = a3;
    } else {
        float dv = g_dinv[node];
        v0 = dv * fmaxf(fmaf(a0, dv, __ldg(bias + li * HPL + 0)), 0.f);
        v1 = dv * fmaxf(fmaf(a1, dv, __ldg(bias + li * HPL + 1)), 0.f);
        v2 = dv * fmaxf(fmaf(a2, dv, __ldg(bias + li * HPL + 2)), 0.f);
        v3 = dv * fmaxf(fmaf(a3, dv, __ldg(bias + li * HPL + 3)), 0.f);
    }
    __half2 h01 = __floats2half2_rn(v0, v1);
    __half2 h23 = __floats2half2_rn(v2, v3);
    *(uint2*)(gdst + (size_t)node * FO + li * HPL) =
        make_uint2(*(uint32_t*)&h01, *(uint32_t*)&h23);
}

// ---------------------------------------------------------------------------
// Host launcher
// ---------------------------------------------------------------------------
template <int FI, int FO, int PRO, int EPI>
static void launch_tgemm(const __half* inh, const float* inf, const float* W,
                         const float* bepi, __half* outh, float* outf, int n)
{
    constexpr int SM = (64 * (FI + 8) + FI * (FO + 8)) * 2;
    cudaFuncSetAttribute((const void*)k_tgemm<FI, FO, PRO, EPI>,
                         cudaFuncAttributeMaxDynamicSharedMemorySize, SM);
    k_tgemm<FI, FO, PRO, EPI><<<(n + 63) / 64, 128, SM>>>(inh, inf, W, bepi, outh, outf, n);
}

template <int FO, int GM>
static void launch_gather(const __half* src, __half* dst, const float* bias, int n)
{
    constexpr int NPW = 32 / (FO / 4);
    int warps  = (n + NPW - 1) / NPW;
    int blocks = (warps + 7) / 8;
    k_gather<FO, GM><<<blocks, 256>>>(src, dst, bias, n);
}

extern "C" void kernel_launch(void* const* d_in, const int* in_sizes, int n_in,
                              void* d_out, int out_size)
{
    const float* x  = (const float*)d_in[0];
    const int*   ei = (const int*)d_in[1];
    const int n = in_sizes[0] / 128;
    const int E = in_sizes[1] / 2;
    const int* row = ei;        // source j
    const int* col = ei + E;    // target i

    const float* W1 = (const float*)d_in[3];  const float* b1 = (const float*)d_in[4];
    const float* W2 = (const float*)d_in[5];  const float* b2 = (const float*)d_in[6];
    const float* W3 = (const float*)d_in[7];  const float* b3 = (const float*)d_in[8];
    const float* W4 = (const float*)d_in[9];  const float* b4 = (const float*)d_in[10];
    const float* W5 = (const float*)d_in[11]; const float* b5 = (const float*)d_in[12];
    const float* W6 = (const float*)d_in[13]; const float* b6 = (const float*)d_in[14];
    const float* Wf = (const float*)d_in[15]; const float* bf = (const float*)d_in[16];

    __half *A, *B; int* degPtr;
    cudaGetSymbolAddress((void**)&A, g_bufA);
    cudaGetSymbolAddress((void**)&B, g_bufB);
    cudaGetSymbolAddress((void**)&degPtr, g_deg);
    float* dout = (float*)d_out;

    // Degree + dinv + CSR (recomputed every replay: deterministic, capture-safe)
    cudaMemsetAsync(degPtr, 0, (size_t)n * sizeof(int));
    int tE8 = (E + 7) / 8;
    k_count<<<(tE8 + 255) / 256, 256>>>(col, E);
    int nb = (n + 1023) / 1024;
    k_scan1<<<nb, 1024>>>(n);
    k_finish<<<(n + 255) / 256, 256>>>(n, E, nb);
    k_fill<<<(tE8 + 255) / 256, 256>>>(row, col, E);

    // L1 (TF, 128->64): t1 = (dinv*x)@W1 ; gather -> u2 = dinv*relu(dinv*S+b1)
    launch_tgemm<128, 64, 2, 0>(nullptr, x, W1, nullptr, A, nullptr, n);
    launch_gather<64, 1>(A, B, b1, n);

    // L2 (TF, 64->32): t2 = u2@W2 ; gather -> u3
    launch_tgemm<64, 32, 0, 0>(B, nullptr, W2, nullptr, A, nullptr, n);
    launch_gather<32, 1>(A, B, b2, n);

    // L3 (TF, 32->16): t3 = u3@W3 ; gather -> u4
    launch_tgemm<32, 16, 0, 0>(B, nullptr, W3, nullptr, A, nullptr, n);
    launch_gather<16, 1>(A, B, b3, n);

    // L4 (AF, 16->32): gather u4 -> U4 ; GEMM epi1(b4) -> u5
    launch_gather<16, 0>(B, A, nullptr, n);
    launch_tgemm<16, 32, 0, 1>(A, nullptr, W4, b4, B, nullptr, n);

    // L5 (AF, 32->64): gather u5 -> U5 ; GEMM epi1(b5) -> u6
    launch_gather<32, 0>(B, A, nullptr, n);
    launch_tgemm<32, 64, 0, 1>(A, nullptr, W5, b5, B, nullptr, n);

    // L6 (AF, 64->128): gather u6 -> U6 ; GEMM epi2(b6) -> a7 = relu(dinv*dot+b6)
    launch_gather<64, 0>(B, A, nullptr, n);
    launch_tgemm<64, 128, 0, 2>(A, nullptr, W6, b6, B, nullptr, n);

    // Final: out = a7@Wf + bf (fp32)
    launch_tgemm<128, 128, 0, 3>(B, nullptr, Wf, bf, nullptr, dout, n);
}

// round 16
// speedup vs baseline: 1.0450x; 1.0450x over previous
#include <cuda_runtime.h>
#include <cuda_fp16.h>
#include <cstdint>
#include <cstddef>

#define MAXN 100000
#define MAXE 3200000

// Scratch (device globals: allocation-free, rewritten every replay)
__device__ __half g_bufA[MAXN * 128];  // fp16 ping
__device__ __half g_bufB[MAXN * 128];  // fp16 pong
__device__ float  g_dinv[MAXN];
__device__ int    g_deg[MAXN];
__device__ int    g_offs[MAXN + 1];
__device__ int    g_cur[MAXN];
__device__ int    g_csr[MAXE];         // edge sources grouped by destination
__device__ int    g_part[128];

__device__ __forceinline__ uint32_t smem_u32(const void* p) {
    return (uint32_t)__cvta_generic_to_shared(p);
}

// ---------------------------------------------------------------------------
// Degree / dinv / CSR build  (deg zeroed by cudaMemsetAsync host-side)
// 1 edge per thread (R11 best: L2-atomic-throughput bound; batching regressed)
// ---------------------------------------------------------------------------
__global__ void k_count(const int* __restrict__ col, int E) {
    int i = blockIdx.x * blockDim.x + threadIdx.x;
    if (i < E) atomicAdd(&g_deg[col[i]], 1);
}

__global__ __launch_bounds__(1024) void k_scan1(int n) {
    __shared__ int sh[1024];
    int i = blockIdx.x * 1024 + threadIdx.x;
    int v = (i < n) ? g_deg[i] : 0;
    sh[threadIdx.x] = v;
    __syncthreads();
    for (int d = 1; d < 1024; d <<= 1) {
        int t = (threadIdx.x >= d) ? sh[threadIdx.x - d] : 0;
        __syncthreads();
        sh[threadIdx.x] += t;
        __syncthreads();
    }
    if (i < n) g_offs[i] = sh[threadIdx.x] - v;  // exclusive within block
    if (threadIdx.x == 1023) g_part[blockIdx.x] = sh[1023];
}

// Merged: scan block partials (redundantly per block), add offset,
// cursor = start offset, dinv, sentinel.
__global__ __launch_bounds__(256) void k_finish(int n, int E, int nb) {
    __shared__ int sp[128];
    int tid = threadIdx.x;
    if (tid < 128) sp[tid] = (tid < nb) ? g_part[tid] : 0;
    __syncthreads();
    for (int d = 1; d < 128; d <<= 1) {
        int t = 0;
        if (tid < 128 && tid >= d) t = sp[tid - d];
        __syncthreads();
        if (tid < 128) sp[tid] += t;
        __syncthreads();
    }
    int i = blockIdx.x * 256 + tid;
    if (i < n) {
        int b = i >> 10;
        int off = (b == 0) ? 0 : sp[b - 1];
        int o = g_offs[i] + off;
        g_offs[i] = o;
        g_cur[i]  = o;  // fill cursor starts at segment base
        g_dinv[i] = rsqrtf((float)g_deg[i] + 1.0f);
    }
    if (i == 0) g_offs[n] = E;
}

__global__ void k_fill(const int* __restrict__ row, const int* __restrict__ col, int E) {
    int e = blockIdx.x * blockDim.x + threadIdx.x;
    if (e < E) {
        int p = atomicAdd(&g_cur[col[e]], 1);
        g_csr[p] = row[e];
    }
}

// ---------------------------------------------------------------------------
// Tensor-core GEMM (mma.sync m16n8k16, f16 x f16 -> f32).
// Block = 128 threads (4 warps), tile = 64 nodes x FO.
// PRO 0: A = fp16 input raw.     PRO 2: A = f16(dinv * fp32 input)   (L1)
// EPI 0: outh = f16(dot)
// EPI 1: outh = f16(dinv * relu(dinv * dot + bepi))
// EPI 2: outh = f16(relu(dinv * dot + bepi))
// EPI 3: outf = dot + bepi
// ---------------------------------------------------------------------------
template <int FI, int FO, int PRO, int EPI>
__global__ __launch_bounds__(128)
void k_tgemm(const __half* __restrict__ inh, const float* __restrict__ inf,
             const float* __restrict__ W, const float* __restrict__ bepi,
             __half* __restrict__ outh, float* __restrict__ outf, int n)
{
    constexpr int SA = FI + 8;
    constexpr int SW = FO + 8;
    extern __shared__ char smraw[];
    __half* sA = (__half*)smraw;            // 64 x SA
    __half* sW = (__half*)smraw + 64 * SA;  // FI x SW

    const int tid   = threadIdx.x;
    const int node0 = blockIdx.x * 64;

    if (PRO == 0) {
        for (int i = tid; i < 64 * (FI / 8); i += 128) {
            int node = i / (FI / 8);
            int f8   = i % (FI / 8);
            int gn   = node0 + node;
            uint4 v = make_uint4(0, 0, 0, 0);
            if (gn < n) v = *(const uint4*)(inh + (size_t)gn * FI + f8 * 8);
            *(uint4*)(sA + node * SA + f8 * 8) = v;
        }
    } else {
        for (int i = tid; i < 64 * (FI / 4); i += 128) {
            int node = i / (FI / 4);
            int fc   = i % (FI / 4);
            int f    = fc * 4;
            int gn   = node0 + node;
            float4 v = make_float4(0.f, 0.f, 0.f, 0.f);
            float dv = 0.f;
            if (gn < n) {
                v = *(const float4*)(inf + (size_t)gn * FI + f);
                dv = g_dinv[gn];
            }
            __half2 h01 = __floats2half2_rn(v.x * dv, v.y * dv);
            __half2 h23 = __floats2half2_rn(v.z * dv, v.w * dv);
            *(uint2*)(sA + node * SA + f) = make_uint2(*(uint32_t*)&h01, *(uint32_t*)&h23);
        }
    }
    for (int i = tid; i < FI * (FO / 4); i += 128) {
        int k  = i / (FO / 4);
        int nc = i % (FO / 4);
        int nn = nc * 4;
        float4 w = __ldg((const float4*)(W + (size_t)k * FO + nn));
        __half2 h01 = __floats2half2_rn(w.x, w.y);
        __half2 h23 = __floats2half2_rn(w.z, w.w);
        *(uint2*)(sW + k * SW + nn) = make_uint2(*(uint32_t*)&h01, *(uint32_t*)&h23);
    }
    __syncthreads();

    const int w    = tid >> 5;
    const int lane = tid & 31;
    constexpr int NT = FO / 8;

    float acc[NT][4];
    #pragma unroll
    for (int t = 0; t < NT; t++) {
        acc[t][0] = 0.f; acc[t][1] = 0.f; acc[t][2] = 0.f; acc[t][3] = 0.f;
    }

    const uint32_t aBase = smem_u32(sA);
    const uint32_t wBase = smem_u32(sW);
    const int arow = w * 16 + (lane & 15);
    const int asel = (lane >> 4) * 8;

    #pragma unroll
    for (int kk = 0; kk < FI / 16; kk++) {
        uint32_t a0, a1, a2, a3;
        {
            uint32_t addrA = aBase + (uint32_t)((arow * SA + kk * 16 + asel) * 2);
            asm volatile("ldmatrix.sync.aligned.m8n8.x4.shared.b16 {%0,%1,%2,%3}, [%4];"
                         : "=r"(a0), "=r"(a1), "=r"(a2), "=r"(a3) : "r"(addrA));
        }
        const int krow = kk * 16 + (lane & 15);
        #pragma unroll
        for (int nt = 0; nt < NT; nt++) {
            uint32_t b0, b1;
            uint32_t addrB = wBase + (uint32_t)((krow * SW + nt * 8) * 2);
            asm volatile("ldmatrix.sync.aligned.m8n8.x2.trans.shared.b16 {%0,%1}, [%2];"
                         : "=r"(b0), "=r"(b1) : "r"(addrB));
            asm volatile("mma.sync.aligned.m16n8k16.row.col.f32.f16.f16.f32 "
                         "{%0,%1,%2,%3}, {%4,%5,%6,%7}, {%8,%9}, {%0,%1,%2,%3};"
                         : "+f"(acc[nt][0]), "+f"(acc[nt][1]),
                           "+f"(acc[nt][2]), "+f"(acc[nt][3])
                         : "r"(a0), "r"(a1), "r"(a2), "r"(a3), "r"(b0), "r"(b1));
        }
    }

    const int g8 = lane >> 2;
    const int t2 = (lane & 3) * 2;
    const int r0 = node0 + w * 16 + g8;
    const int r1 = r0 + 8;
    float dv0 = 0.f, dv1 = 0.f;
    if (EPI == 1 || EPI == 2) {
        if (r0 < n) dv0 = g_dinv[r0];
        if (r1 < n) dv1 = g_dinv[r1];
    }
    #pragma unroll
    for (int nt = 0; nt < NT; nt++) {
        int c = nt * 8 + t2;
        float d0 = acc[nt][0], d1 = acc[nt][1], d2 = acc[nt][2], d3 = acc[nt][3];
        if (EPI == 0) {
            if (r0 < n) {
                __half2 hh = __floats2half2_rn(d0, d1);
                *(uint32_t*)(outh + (size_t)r0 * FO + c) = *(uint32_t*)&hh;
            }
            if (r1 < n) {
                __half2 hh = __floats2half2_rn(d2, d3);
                *(uint32_t*)(outh + (size_t)r1 * FO + c) = *(uint32_t*)&hh;
            }
        } else if (EPI == 1 || EPI == 2) {
            float bc0 = __ldg(bepi + c), bc1 = __ldg(bepi + c + 1);
            if (r0 < n) {
                float v0 = fmaxf(fmaf(d0, dv0, bc0), 0.f);
                float v1 = fmaxf(fmaf(d1, dv0, bc1), 0.f);
                if (EPI == 1) { v0 *= dv0; v1 *= dv0; }
                __half2 hh = __floats2half2_rn(v0, v1);
                *(uint32_t*)(outh + (size_t)r0 * FO + c) = *(uint32_t*)&hh;
            }
            if (r1 < n) {
                float v0 = fmaxf(fmaf(d2, dv1, bc0), 0.f);
                float v1 = fmaxf(fmaf(d3, dv1, bc1), 0.f);
                if (EPI == 1) { v0 *= dv1; v1 *= dv1; }
                __half2 hh = __floats2half2_rn(v0, v1);
                *(uint32_t*)(outh + (size_t)r1 * FO + c) = *(uint32_t*)&hh;
            }
        } else {
            float add0 = __ldg(bepi + c), add1 = __ldg(bepi + c + 1);
            if (r0 < n) *(float2*)(outf + (size_t)r0 * FO + c) = make_float2(d0 + add0, d1 + add1);
            if (r1 < n) *(float2*)(outf + (size_t)r1 * FO + c) = make_float2(d2 + add0, d3 + add1);
        }
    }
}

// ---------------------------------------------------------------------------
// CSR gather-reduce (fp16 in, fp32 accumulate, fp16 out).
// HPL = halves per lane: 8 (16B loads) for FO>=32, 4 (8B) for FO=16.
// GM 0: out = f16(s)          GM 1: out = f16(dinv * relu(dinv * s + bias))
// ---------------------------------------------------------------------------
template <int FO, int GM, int HPL>
__global__ __launch_bounds__(256)
void k_gather(const __half* __restrict__ gsrc, __half* __restrict__ gdst,
              const float* __restrict__ bias, int n)
{
    constexpr int LPN = FO / HPL;          // lanes per node
    constexpr int NPW = 32 / LPN;          // nodes per warp
    constexpr int UN  = (HPL == 8) ? 4 : 8;

    int warp = (blockIdx.x * 256 + threadIdx.x) >> 5;
    int lane = threadIdx.x & 31;
    int node = warp * NPW + lane / LPN;
    if (node >= n) return;
    int li  = lane % LPN;
    int beg = g_offs[node];
    int end = g_offs[node + 1];

    const __half* base = gsrc + li * HPL;

    auto fetch = [&](int s, float* x) {
        if (HPL == 4) {
            uint2 u = __ldg((const uint2*)(base + (size_t)s * FO));
            float2 f0 = __half22float2(*(__half2*)&u.x);
            float2 f1 = __half22float2(*(__half2*)&u.y);
            x[0] = f0.x; x[1] = f0.y; x[2] = f1.x; x[3] = f1.y;
        } else {
            uint4 u = __ldg((const uint4*)(base + (size_t)s * FO));
            float2 f0 = __half22float2(*(__half2*)&u.x);
            float2 f1 = __half22float2(*(__half2*)&u.y);
            float2 f2 = __half22float2(*(__half2*)&u.z);
            float2 f3 = __half22float2(*(__half2*)&u.w);
            x[0] = f0.x; x[1] = f0.y; x[2] = f1.x; x[3] = f1.y;
            x[4] = f2.x; x[5] = f2.y; x[6] = f3.x; x[7] = f3.y;
        }
    };

    float a[HPL];
    fetch(node, a);   // self term

    int e = beg;
    while (e < end && (e & 3)) {
        float x[HPL];
        fetch(__ldg(g_csr + e), x);
        #pragma unroll
        for (int h = 0; h < HPL; h++) a[h] += x[h];
        e++;
    }

    for (; e + UN - 1 < end; e += UN) {
        int idx[UN];
        {
            int4 iv = __ldg((const int4*)(g_csr + e));
            idx[0] = iv.x; idx[1] = iv.y; idx[2] = iv.z; idx[3] = iv.w;
        }
        if (UN == 8) {
            int4 iv = __ldg((const int4*)(g_csr + e + 4));
            idx[4] = iv.x; idx[5] = iv.y; idx[6] = iv.z; idx[7] = iv.w;
        }
        float x[UN][HPL];
        #pragma unroll
        for (int q = 0; q < UN; q++) fetch(idx[q], x[q]);
        #pragma unroll
        for (int h = 0; h < HPL; h++) {
            if (UN == 4) {
                a[h] += (x[0][h] + x[1][h]) + (x[2][h] + x[3][h]);
            } else {
                a[h] += ((x[0][h] + x[1][h]) + (x[2][h] + x[3][h]))
                      + ((x[4][h] + x[5][h]) + (x[6][h] + x[7][h]));
            }
        }
    }
    for (; e < end; e++) {
        float x[HPL];
        fetch(__ldg(g_csr + e), x);
        #pragma unroll
        for (int h = 0; h < HPL; h++) a[h] += x[h];
    }

    float v[HPL];
    if (GM == 0) {
        #pragma unroll
        for (int h = 0; h < HPL; h++) v[h] = a[h];
    } else {
        float dv = g_dinv[node];
        #pragma unroll
        for (int h = 0; h < HPL; h++)
            v[h] = dv * fmaxf(fmaf(a[h], dv, __ldg(bias + li * HPL + h)), 0.f);
    }
    uint32_t packed[HPL / 2];
    #pragma unroll
    for (int h = 0; h < HPL / 2; h++) {
        __half2 hh = __floats2half2_rn(v[2 * h], v[2 * h + 1]);
        packed[h] = *(uint32_t*)&hh;
    }
    __half* dst = gdst + (size_t)node * FO + li * HPL;
    if (HPL == 4) *(uint2*)dst = make_uint2(packed[0], packed[1]);
    else          *(uint4*)dst = make_uint4(packed[0], packed[1], packed[2], packed[3]);
}

// ---------------------------------------------------------------------------
// Host launcher
// ---------------------------------------------------------------------------
template <int FI, int FO, int PRO, int EPI>
static void launch_tgemm(const __half* inh, const float* inf, const float* W,
                         const float* bepi, __half* outh, float* outf, int n)
{
    constexpr int SM = (64 * (FI + 8) + FI * (FO + 8)) * 2;
    cudaFuncSetAttribute((const void*)k_tgemm<FI, FO, PRO, EPI>,
                         cudaFuncAttributeMaxDynamicSharedMemorySize, SM);
    k_tgemm<FI, FO, PRO, EPI><<<(n + 63) / 64, 128, SM>>>(inh, inf, W, bepi, outh, outf, n);
}

template <int FO, int GM>
static void launch_gather(const __half* src, __half* dst, const float* bias, int n)
{
    constexpr int HPL = (FO >= 32) ? 8 : 4;
    constexpr int NPW = 32 / (FO / HPL);
    int warps  = (n + NPW - 1) / NPW;
    int blocks = (warps + 7) / 8;
    k_gather<FO, GM, HPL><<<blocks, 256>>>(src, dst, bias, n);
}

extern "C" void kernel_launch(void* const* d_in, const int* in_sizes, int n_in,
                              void* d_out, int out_size)
{
    const float* x  = (const float*)d_in[0];
    const int*   ei = (const int*)d_in[1];
    const int n = in_sizes[0] / 128;
    const int E = in_sizes[1] / 2;
    const int* row = ei;        // source j
    const int* col = ei + E;    // target i

    const float* W1 = (const float*)d_in[3];  const float* b1 = (const float*)d_in[4];
    const float* W2 = (const float*)d_in[5];  const float* b2 = (const float*)d_in[6];
    const float* W3 = (const float*)d_in[7];  const float* b3 = (const float*)d_in[8];
    const float* W4 = (const float*)d_in[9];  const float* b4 = (const float*)d_in[10];
    const float* W5 = (const float*)d_in[11]; const float* b5 = (const float*)d_in[12];
    const float* W6 = (const float*)d_in[13]; const float* b6 = (const float*)d_in[14];
    const float* Wf = (const float*)d_in[15]; const float* bf = (const float*)d_in[16];

    __half *A, *B; int* degPtr;
    cudaGetSymbolAddress((void**)&A, g_bufA);
    cudaGetSymbolAddress((void**)&B, g_bufB);
    cudaGetSymbolAddress((void**)&degPtr, g_deg);
    float* dout = (float*)d_out;

    // Degree + dinv + CSR (recomputed every replay: deterministic, capture-safe)
    cudaMemsetAsync(degPtr, 0, (size_t)n * sizeof(int));
    k_count<<<(E + 255) / 256, 256>>>(col, E);
    int nb = (n + 1023) / 1024;
    k_scan1<<<nb, 1024>>>(n);
    k_finish<<<(n + 255) / 256, 256>>>(n, E, nb);
    k_fill<<<(E + 255) / 256, 256>>>(row, col, E);

    // L1 (TF, 128->64): t1 = (dinv*x)@W1 ; gather -> u2 = dinv*relu(dinv*S+b1)
    launch_tgemm<128, 64, 2, 0>(nullptr, x, W1, nullptr, A, nullptr, n);
    launch_gather<64, 1>(A, B, b1, n);

    // L2 (TF, 64->32): t2 = u2@W2 ; gather -> u3
    launch_tgemm<64, 32, 0, 0>(B, nullptr, W2, nullptr, A, nullptr, n);
    launch_gather<32, 1>(A, B, b2, n);

    // L3 (TF, 32->16): t3 = u3@W3 ; gather -> u4
    launch_tgemm<32, 16, 0, 0>(B, nullptr, W3, nullptr, A, nullptr, n);
    launch_gather<16, 1>(A, B, b3, n);

    // L4 (AF, 16->32): gather u4 -> U4 ; GEMM epi1(b4) -> u5
    launch_gather<16, 0>(B, A, nullptr, n);
    launch_tgemm<16, 32, 0, 1>(A, nullptr, W4, b4, B, nullptr, n);

    // L5 (AF, 32->64): gather u5 -> U5 ; GEMM epi1(b5) -> u6
    launch_gather<32, 0>(B, A, nullptr, n);
    launch_tgemm<32, 64, 0, 1>(A, nullptr, W5, b5, B, nullptr, n);

    // L6 (AF, 64->128): gather u6 -> U6 ; GEMM epi2(b6) -> a7 = relu(dinv*dot+b6)
    launch_gather<64, 0>(B, A, nullptr, n);
    launch_tgemm<64, 128, 0, 2>(A, nullptr, W6, b6, B, nullptr, n);

    // Final: out = a7@Wf + bf (fp32)
    launch_tgemm<128, 128, 0, 3>(B, nullptr, Wf, bf, nullptr, dout, n);
}